// round 1
// baseline (speedup 1.0000x reference)
#include <cuda_runtime.h>
#include <cuda_bf16.h>
#include <math_constants.h>

#define Bsz 1024
#define Ssz 128
#define NW (Bsz*Ssz)   // 131072 words

// scratch (static device allocations are allowed)
__device__ float g_xg[2][(size_t)NW*24];  // pre-activations Wih@x + b, per direction
__device__ float g_h[(size_t)NW*12];      // bi-LSTM hidden output [B,S,2H]

__device__ __forceinline__ float sigmoidf_(float x){ return 1.f/(1.f+__expf(-x)); }
__device__ __forceinline__ float tanh_fast(float x){ float y; asm("tanh.approx.f32 %0, %1;" : "=f"(y) : "f"(x)); return y; }

// ---------------- Kernel 1: char-CNN + embeddings + xgate precompute ----------------
__global__ __launch_bounds__(256) void k1_embed(
    const int* __restrict__ word_idx, const int* __restrict__ char_idx,
    const float* __restrict__ word_emb, const float* __restrict__ char_emb,
    const float* __restrict__ Wc, const float* __restrict__ bc,
    const float* __restrict__ Wih_f, const float* __restrict__ b_f,
    const float* __restrict__ Wih_b, const float* __restrict__ b_b)
{
    __shared__ float s_ce[600];
    __shared__ float s_Wc[72];
    __shared__ float s_bc[4];
    __shared__ float s_Wf[336], s_bf[24], s_Wb[336], s_bb[24];
    int tid = threadIdx.x;
    for (int i=tid;i<600;i+=256) s_ce[i]=char_emb[i];
    for (int i=tid;i<72;i+=256)  s_Wc[i]=Wc[i];
    if (tid<4) s_bc[tid]=bc[tid];
    for (int i=tid;i<336;i+=256){ s_Wf[i]=Wih_f[i]; s_Wb[i]=Wih_b[i]; }
    if (tid<24){ s_bf[tid]=b_f[tid]; s_bb[tid]=b_b[tid]; }
    __syncthreads();

    int w = blockIdx.x*256 + tid;          // exact grid, always valid
    float x[14];
    int widx = word_idx[w];
    const float2* wep = (const float2*)(word_emb) + (size_t)widx*5;
    #pragma unroll
    for (int k=0;k<5;k++){ float2 v = __ldg(wep+k); x[2*k]=v.x; x[2*k+1]=v.y; }

    int ci[14];
    const int* cp = char_idx + (size_t)w*14;
    #pragma unroll
    for (int k=0;k<14;k++) ci[k]=__ldg(cp+k);

    // rolling 3-char window, 4 filters, max-pool over 12 windows
    float e[18];
    #pragma unroll
    for (int m=0;m<6;m++){ e[m]=s_ce[ci[0]*6+m]; e[6+m]=s_ce[ci[1]*6+m]; }
    float a0=-CUDART_INF_F,a1=-CUDART_INF_F,a2=-CUDART_INF_F,a3=-CUDART_INF_F;
    #pragma unroll
    for (int win=0;win<12;win++){
        #pragma unroll
        for (int m=0;m<6;m++) e[12+m]=s_ce[ci[win+2]*6+m];
        float p0=s_bc[0],p1=s_bc[1],p2=s_bc[2],p3=s_bc[3];
        #pragma unroll
        for (int m=0;m<18;m++){
            float v=e[m];
            p0 = fmaf(v, s_Wc[0*18+m], p0);
            p1 = fmaf(v, s_Wc[1*18+m], p1);
            p2 = fmaf(v, s_Wc[2*18+m], p2);
            p3 = fmaf(v, s_Wc[3*18+m], p3);
        }
        a0=fmaxf(a0,p0); a1=fmaxf(a1,p1); a2=fmaxf(a2,p2); a3=fmaxf(a3,p3);
        #pragma unroll
        for (int m=0;m<12;m++) e[m]=e[m+6];
    }
    x[10]=a0; x[11]=a1; x[12]=a2; x[13]=a3;

    // xgate forward
    float xg[24];
    #pragma unroll
    for (int g=0; g<24; g++){
        float acc = s_bf[g];
        #pragma unroll
        for (int k=0;k<14;k++) acc = fmaf(x[k], s_Wf[g*14+k], acc);
        xg[g]=acc;
    }
    float4* of = (float4*)(&g_xg[0][(size_t)w*24]);
    #pragma unroll
    for (int q=0;q<6;q++) of[q] = make_float4(xg[4*q],xg[4*q+1],xg[4*q+2],xg[4*q+3]);
    // xgate backward
    #pragma unroll
    for (int g=0; g<24; g++){
        float acc = s_bb[g];
        #pragma unroll
        for (int k=0;k<14;k++) acc = fmaf(x[k], s_Wb[g*14+k], acc);
        xg[g]=acc;
    }
    float4* ob = (float4*)(&g_xg[1][(size_t)w*24]);
    #pragma unroll
    for (int q=0;q<6;q++) ob[q] = make_float4(xg[4*q],xg[4*q+1],xg[4*q+2],xg[4*q+3]);
}

// ---------------- Kernel 2: bidirectional LSTM recurrence ----------------
// one warp per (sentence, direction). lane j < 24 owns gate j (torch order i,f,g,o).
__global__ __launch_bounds__(256) void k2_lstm(
    const float* __restrict__ Whh_f, const float* __restrict__ Whh_b)
{
    const unsigned FULL = 0xffffffffu;
    int wg   = (blockIdx.x*256 + threadIdx.x) >> 5;   // 0..2047
    int lane = threadIdx.x & 31;
    int b    = wg >> 1;
    int dir  = wg & 1;
    int jc   = (lane < 24) ? lane : 0;
    int gl   = (lane < 6) ? lane : 0;
    bool is_g = (lane >= 12 && lane < 18);

    const float* Whh = dir ? Whh_b : Whh_f;
    float w0=__ldg(Whh+jc*6+0), w1=__ldg(Whh+jc*6+1), w2=__ldg(Whh+jc*6+2),
          w3=__ldg(Whh+jc*6+3), w4=__ldg(Whh+jc*6+4), w5=__ldg(Whh+jc*6+5);

    const float* xg = g_xg[dir] + (size_t)b*Ssz*24;
    float* hout = g_h + (size_t)b*Ssz*12 + dir*6;

    float h0=0.f,h1=0.f,h2=0.f,h3=0.f,h4=0.f,h5=0.f,c=0.f;
    int s  = dir ? (Ssz-1) : 0;
    int ds = dir ? -1 : 1;

    float gx = __ldg(xg + s*24 + jc);  // prefetched pre-activation
    for (int t=0; t<Ssz; t++){
        float gcur = gx;
        int sn = s + ds;
        if (t+1 < Ssz) gx = __ldg(xg + sn*24 + jc);  // prefetch next step

        float g = fmaf(w0,h0,gcur);
        g = fmaf(w1,h1,g); g = fmaf(w2,h2,g); g = fmaf(w3,h3,g);
        g = fmaf(w4,h4,g); g = fmaf(w5,h5,g);
        float act = is_g ? tanh_fast(g) : sigmoidf_(g);

        float ai = __shfl_sync(FULL, act, gl);
        float af = __shfl_sync(FULL, act, gl+6);
        float ag = __shfl_sync(FULL, act, gl+12);
        float ao = __shfl_sync(FULL, act, gl+18);
        c = fmaf(af, c, ai*ag);
        float hj = ao * tanh_fast(c);

        h0=__shfl_sync(FULL,hj,0); h1=__shfl_sync(FULL,hj,1); h2=__shfl_sync(FULL,hj,2);
        h3=__shfl_sync(FULL,hj,3); h4=__shfl_sync(FULL,hj,4); h5=__shfl_sync(FULL,hj,5);

        if (lane < 6) hout[s*12 + lane] = hj;
        s = sn;
    }
}

// ---------------- Kernel 3: tag linear + log_softmax ----------------
// warp per (b,s) pair, 16 pairs per warp to amortize the shared Wt load.
__global__ __launch_bounds__(256) void k3_tag(
    const float* __restrict__ Wt, const float* __restrict__ bt, float* __restrict__ out)
{
    __shared__ float sW[12*136];   // transposed + padded: sW[k*136 + j], conflict-free
    __shared__ float sb[136];
    int tid = threadIdx.x;
    for (int i=tid;i<1620;i+=256){ int j=i/12, k=i%12; sW[k*136+j]=Wt[i]; }
    if (tid<135) sb[tid]=bt[tid];
    __syncthreads();

    int warp = tid>>5, lane = tid&31;
    int base = (blockIdx.x*8 + warp)*16;
    for (int it=0; it<16; it++){
        int p = base + it;
        const float* hp = g_h + (size_t)p*12;
        float h[12];
        #pragma unroll
        for (int k=0;k<12;k++) h[k]=__ldg(hp+k);

        float tg[5];
        float m = -CUDART_INF_F;
        #pragma unroll
        for (int t5=0;t5<5;t5++){
            int j = lane + 32*t5;
            float v = -CUDART_INF_F;
            if (j < 135){
                v = sb[j];
                #pragma unroll
                for (int k=0;k<12;k++) v = fmaf(h[k], sW[k*136+j], v);
            }
            tg[t5]=v; m=fmaxf(m,v);
        }
        #pragma unroll
        for (int o=16;o>0;o>>=1) m = fmaxf(m, __shfl_xor_sync(0xffffffffu,m,o));
        float zs = 0.f;
        #pragma unroll
        for (int t5=0;t5<5;t5++){ int j=lane+32*t5; if (j<135) zs += __expf(tg[t5]-m); }
        #pragma unroll
        for (int o=16;o>0;o>>=1) zs += __shfl_xor_sync(0xffffffffu,zs,o);
        float lse = m + __logf(zs);
        float* op = out + (size_t)p*135;
        #pragma unroll
        for (int t5=0;t5<5;t5++){ int j=lane+32*t5; if (j<135) op[j]=tg[t5]-lse; }
    }
}

// ---------------- Launch ----------------
extern "C" void kernel_launch(void* const* d_in, const int* in_sizes, int n_in,
                              void* d_out, int out_size)
{
    // Bind inputs by element count (robust to metadata ordering; forward comes
    // before backward for the duplicated sizes in both plausible orderings).
    const int *word_idx=nullptr,*char_idx=nullptr;
    const float *word_emb=nullptr,*char_emb=nullptr,*Wc=nullptr,*bc=nullptr,
        *Wih_f=nullptr,*Whh_f=nullptr,*b_f=nullptr,
        *Wih_b=nullptr,*Whh_b=nullptr,*b_b=nullptr,*Wt=nullptr,*bt=nullptr;
    for (int i=0;i<n_in;i++){
        int sz = in_sizes[i]; const void* p = d_in[i];
        switch (sz){
            case 131072:  word_idx=(const int*)p; break;          // [B,S]
            case 1835008: char_idx=(const int*)p; break;          // [B,S,LP]
            case 500000:  word_emb=(const float*)p; break;        // [V,WE]
            case 600:     char_emb=(const float*)p; break;        // [A,CE]
            case 72:      Wc=(const float*)p; break;              // [Lf,K*CE]
            case 4:       bc=(const float*)p; break;              // [Lf]
            case 336:     if(!Wih_f) Wih_f=(const float*)p; else Wih_b=(const float*)p; break;
            case 144:     if(!Whh_f) Whh_f=(const float*)p; else Whh_b=(const float*)p; break;
            case 24:      if(!b_f)   b_f  =(const float*)p; else b_b  =(const float*)p; break;
            case 1620:    Wt=(const float*)p; break;              // [T,2H]
            case 135:     bt=(const float*)p; break;              // [T]
        }
    }

    k1_embed<<<NW/256, 256>>>(word_idx, char_idx, word_emb, char_emb,
                              Wc, bc, Wih_f, b_f, Wih_b, b_b);
    k2_lstm<<<(2*Bsz*32)/256, 256>>>(Whh_f, Whh_b);   // 2048 warps
    k3_tag<<<NW/128, 256>>>(Wt, bt, (float*)d_out);
    (void)out_size; (void)n_in;
}